// round 11
// baseline (speedup 1.0000x reference)
#include <cuda_runtime.h>
#include <cuda_fp16.h>
#include <cstdint>

// PowerSoftmax attention: int8-split QK (mma.m16n8k32.s8) + fp16 PV,
// all conversion in-kernel (R7 phase structure, no cp.async).
//   S = (Q K^T)/8 ; P = S^2 ; O = (P / (rowsum(P)+1e-6)) V
// 64 heads of [2048, 64] fp32.
//
// Q,K: per-row 2-term int8 quant (hi = rint(v/s), lo = rint(residual*254/s)),
//      3 cross products, 2 s32 accumulators -> S err ~5e-5.
// P,V: fp16 (dominant error ~3e-4, under the 1e-3 gate).
// Q A-fragments + scales live in registers for the whole kv sweep.

#define NQ       2048
#define DDIM     64
#define BM       128
#define BKV      128
#define NITER    (NQ / BKV)
#define NTHREADS 256

// smem (single buffer, 33 KB)
#define B_KHI  0          // K hi fragment image   8 KB
#define B_KLO  8192       // K lo fragment image   8 KB
#define B_SB   16384      // K row scales          512 B
#define B_V    16896      // Vt[d][kv] fp16        16 KB
#define SMEM_BYTES 33280
// Prologue reuses [0, 16896) for Q fragment staging + Q scales.

// Vt tile: [64 rows][128 kv x 2B = 256B], swizzled
__device__ __forceinline__ uint32_t sw_v(int row, int cb) {
    return (uint32_t)(row * 256 + (cb ^ ((row & 7) << 4)));
}

__device__ __forceinline__ void ldsm_x4(uint32_t* r, uint32_t addr) {
    asm volatile("ldmatrix.sync.aligned.m8n8.x4.shared.b16 {%0,%1,%2,%3}, [%4];"
                 : "=r"(r[0]), "=r"(r[1]), "=r"(r[2]), "=r"(r[3]) : "r"(addr));
}
__device__ __forceinline__ void lds64(uint32_t* r, uint32_t addr) {
    asm volatile("ld.shared.v2.u32 {%0,%1}, [%2];"
                 : "=r"(r[0]), "=r"(r[1]) : "r"(addr));
}
__device__ __forceinline__ void lds64f(float* r, uint32_t addr) {
    asm volatile("ld.shared.v2.f32 {%0,%1}, [%2];"
                 : "=f"(r[0]), "=f"(r[1]) : "r"(addr));
}
__device__ __forceinline__ void mma_f16(float* c, const uint32_t* a, const uint32_t* b) {
    asm volatile("mma.sync.aligned.m16n8k16.row.col.f32.f16.f16.f32 "
                 "{%0,%1,%2,%3}, {%4,%5,%6,%7}, {%8,%9}, {%0,%1,%2,%3};"
                 : "+f"(c[0]), "+f"(c[1]), "+f"(c[2]), "+f"(c[3])
                 : "r"(a[0]), "r"(a[1]), "r"(a[2]), "r"(a[3]), "r"(b[0]), "r"(b[1]));
}
__device__ __forceinline__ void mma_s8(int* c, const uint32_t* a, const uint32_t* b) {
    asm volatile("mma.sync.aligned.m16n8k32.row.col.s32.s8.s8.s32 "
                 "{%0,%1,%2,%3}, {%4,%5,%6,%7}, {%8,%9}, {%0,%1,%2,%3};"
                 : "+r"(c[0]), "+r"(c[1]), "+r"(c[2]), "+r"(c[3])
                 : "r"(a[0]), "r"(a[1]), "r"(a[2]), "r"(a[3]), "r"(b[0]), "r"(b[1]));
}

// pack 4 int8 (values in [-127,127]) into one word
__device__ __forceinline__ uint32_t pack4(int a, int b, int c, int d) {
    return (uint32_t)(a & 255) | ((uint32_t)(b & 255) << 8) |
           ((uint32_t)(c & 255) << 16) | ((uint32_t)(d & 255) << 24);
}

__global__ __launch_bounds__(NTHREADS, 2)
void power_attn_i8(const float* __restrict__ Q, const float* __restrict__ K,
                   const float* __restrict__ V, float* __restrict__ O) {
    extern __shared__ char sm[];
    const uint32_t smb = (uint32_t)__cvta_generic_to_shared(sm);

    const int tid  = threadIdx.x;
    const int lane = tid & 31;
    const int wid  = tid >> 5;
    const int mr   = wid * 16;
    const int g    = lane >> 2;

    const size_t head = (size_t)blockIdx.y * NQ * DDIM;
    const float* qb = Q + head + (size_t)blockIdx.x * BM * DDIM;
    const float* kb = K + head;
    const float* vb = V + head;

    // =================== Prologue: quantize Q, hoist fragments ==============
    {
        const int row = tid >> 1, hs = tid & 1;
        const float4* qr = (const float4*)(qb + (size_t)row * DDIM) + hs * 8;
        float mx = 0.f;
        #pragma unroll
        for (int i = 0; i < 8; ++i) {
            float4 x = qr[i];
            mx = fmaxf(mx, fmaxf(fmaxf(fabsf(x.x), fabsf(x.y)),
                                 fmaxf(fabsf(x.z), fabsf(x.w))));
        }
        mx = fmaxf(mx, __shfl_xor_sync(0xFFFFFFFF, mx, 1));
        float s = fmaxf(mx, 1e-20f) * (1.f / 127.f);
        float inv = 1.f / s, inv2 = 254.f * inv;
        if (hs == 0) *(float*)(sm + B_SB + row * 4) = s;

        const int w = row >> 4, t16 = row & 15;
        const int gq = t16 & 7, half = t16 >> 3;
        #pragma unroll
        for (int i = 0; i < 8; ++i) {
            float4 x = qr[i];
            int ig = hs * 8 + i;
            int c = ig & 3, kh = (ig >> 2) & 1, ks = ig >> 3;
            int h0 = (int)rintf(x.x * inv), h1 = (int)rintf(x.y * inv);
            int h2 = (int)rintf(x.z * inv), h3 = (int)rintf(x.w * inv);
            uint32_t wh = pack4(h0, h1, h2, h3);
            uint32_t wl = pack4((int)rintf((x.x - (float)h0 * s) * inv2),
                                (int)rintf((x.y - (float)h1 * s) * inv2),
                                (int)rintf((x.z - (float)h2 * s) * inv2),
                                (int)rintf((x.w - (float)h3 * s) * inv2));
            int reg = half + kh * 2;
            uint32_t off = (uint32_t)(((w * 2 + ks) * 32 + gq * 4 + c) * 16 + reg * 4);
            *(uint32_t*)(sm + off)        = wh;
            *(uint32_t*)(sm + 8192 + off) = wl;
        }
    }
    __syncthreads();

    uint32_t Qh[2][4], Ql[2][4];
    float SA0p, SA1p;
    {
        #pragma unroll
        for (int ks = 0; ks < 2; ++ks) {
            uint4 a = *(const uint4*)(sm + ((wid * 2 + ks) * 32 + lane) * 16);
            Qh[ks][0] = a.x; Qh[ks][1] = a.y; Qh[ks][2] = a.z; Qh[ks][3] = a.w;
            uint4 b = *(const uint4*)(sm + 8192 + ((wid * 2 + ks) * 32 + lane) * 16);
            Ql[ks][0] = b.x; Ql[ks][1] = b.y; Ql[ks][2] = b.z; Ql[ks][3] = b.w;
        }
        SA0p = *(const float*)(sm + B_SB + (mr + g) * 4)       * 0.125f;
        SA1p = *(const float*)(sm + B_SB + (mr + g + 8) * 4)   * 0.125f;
    }

    float OC[8][4];
    #pragma unroll
    for (int d = 0; d < 8; ++d)
        #pragma unroll
        for (int r = 0; r < 4; ++r) OC[d][r] = 0.f;
    float rs0 = 0.f, rs1 = 0.f;

    const int bx_row = (lane & 7) + ((lane >> 4) << 3);
    const int bx_cbo = ((lane >> 3) & 1) << 4;
    const float C254 = 1.f / 254.f;

    const int krow = tid >> 1, khs = tid & 1;       // K quant: 2 threads/row
    const int kh2  = krow >> 6, knb = (krow >> 3) & 7, kg = krow & 7;
    const int vpart = tid >> 6, vd = tid & 63;      // V convert

    // ============================ KV sweep ==================================
    for (int nt = 0; nt < NITER; ++nt) {
        __syncthreads();                            // prev compute done

        // ---- K quant -> int8 hi/lo fragment image ----
        {
            const float4* kr = (const float4*)(kb + ((size_t)nt * BKV + krow) * DDIM)
                               + khs * 8;
            float mx = 0.f;
            #pragma unroll
            for (int i = 0; i < 8; ++i) {
                float4 x = kr[i];
                mx = fmaxf(mx, fmaxf(fmaxf(fabsf(x.x), fabsf(x.y)),
                                     fmaxf(fabsf(x.z), fabsf(x.w))));
            }
            mx = fmaxf(mx, __shfl_xor_sync(0xFFFFFFFF, mx, 1));
            float s = fmaxf(mx, 1e-20f) * (1.f / 127.f);
            float inv = 1.f / s, inv2 = 254.f * inv;
            if (khs == 0) *(float*)(sm + B_SB + krow * 4) = s;

            #pragma unroll
            for (int i = 0; i < 8; ++i) {
                float4 x = kr[i];
                int c = i & 3, kh = (i >> 2) & 1;   // ks == khs
                int h0 = (int)rintf(x.x * inv), h1 = (int)rintf(x.y * inv);
                int h2 = (int)rintf(x.z * inv), h3 = (int)rintf(x.w * inv);
                uint32_t wh = pack4(h0, h1, h2, h3);
                uint32_t wl = pack4((int)rintf((x.x - (float)h0 * s) * inv2),
                                    (int)rintf((x.y - (float)h1 * s) * inv2),
                                    (int)rintf((x.z - (float)h2 * s) * inv2),
                                    (int)rintf((x.w - (float)h3 * s) * inv2));
                int cs = c ^ (knb & 3);             // bank-spread swizzle
                uint32_t off = (uint32_t)((((kh2 * 2 + khs) * 8 + knb) * 32
                                           + kg * 4 + cs) * 8 + kh * 4);
                *(uint32_t*)(sm + B_KHI + off) = wh;
                *(uint32_t*)(sm + B_KLO + off) = wl;
            }
        }

        // ---- V -> Vt[d][kv] fp16 transposed ----
        {
            const float* vg = vb + (size_t)nt * BKV * DDIM;
            #pragma unroll
            for (int i = 0; i < 16; ++i) {
                int kv = vpart * 32 + i * 2;
                float a = vg[(size_t)kv * DDIM + vd];
                float b = vg[(size_t)(kv + 1) * DDIM + vd];
                __half2 h = __floats2half2_rn(a, b);
                *(uint32_t*)(sm + B_V + sw_v(vd, kv * 2)) = *(uint32_t*)&h;
            }
        }
        __syncthreads();

        // ---- Compute ----
        #pragma unroll
        for (int h = 0; h < 2; ++h) {
            #pragma unroll
            for (int ch = 0; ch < 4; ++ch) {        // chunks of 2 n-blocks
                int accA[2][4], accB[2][4];
                #pragma unroll
                for (int j = 0; j < 2; ++j)
                    #pragma unroll
                    for (int r = 0; r < 4; ++r) { accA[j][r] = 0; accB[j][r] = 0; }

                #pragma unroll
                for (int ks = 0; ks < 2; ++ks) {
                    #pragma unroll
                    for (int j = 0; j < 2; ++j) {
                        int nb = ch * 2 + j;
                        uint32_t off = smb + (uint32_t)(
                            (((h * 2 + ks) * 8 + nb) * 32 + (lane ^ (nb & 3))) * 8);
                        uint32_t bh[2], bl[2];
                        lds64(bh, off + B_KHI);
                        lds64(bl, off + B_KLO);
                        mma_s8(accA[j], Qh[ks], bh);
                        mma_s8(accB[j], Qh[ks], bl);
                        mma_s8(accB[j], Ql[ks], bh);
                    }
                }

                // epilogue: e = SA*SB*(accA + accB/254); p = e^2 -> fp16
                uint32_t P[4];
                #pragma unroll
                for (int j = 0; j < 2; ++j) {
                    int col0 = h * 64 + (ch * 2 + j) * 8 + (lane & 3) * 2;
                    float sb[2];
                    lds64f(sb, smb + B_SB + (uint32_t)(col0 * 4));
                    float m00 = SA0p * sb[0], m01 = SA0p * sb[1];
                    float m10 = SA1p * sb[0], m11 = SA1p * sb[1];
                    float e00 = ((float)accA[j][0] + (float)accB[j][0] * C254) * m00;
                    float e01 = ((float)accA[j][1] + (float)accB[j][1] * C254) * m01;
                    float e10 = ((float)accA[j][2] + (float)accB[j][2] * C254) * m10;
                    float e11 = ((float)accA[j][3] + (float)accB[j][3] * C254) * m11;
                    __half2 h0 = __floats2half2_rn(e00 * e00, e01 * e01);
                    __half2 h1 = __floats2half2_rn(e10 * e10, e11 * e11);
                    float2 f0 = __half22float2(h0);
                    float2 f1 = __half22float2(h1);
                    rs0 += f0.x + f0.y;
                    rs1 += f1.x + f1.y;
                    P[j * 2 + 0] = *(uint32_t*)&h0;
                    P[j * 2 + 1] = *(uint32_t*)&h1;
                }

                // O += P V
                int kvb = (h * 64 + ch * 16) * 2 + bx_cbo;
                #pragma unroll
                for (int dp = 0; dp < 4; ++dp) {
                    uint32_t Bv[4];
                    ldsm_x4(Bv, smb + B_V + sw_v(dp * 16 + bx_row, kvb));
                    mma_f16(OC[2 * dp],     P, Bv + 0);
                    mma_f16(OC[2 * dp + 1], P, Bv + 2);
                }
            }
        }
    }

    // ---- rowsum reduce + store ----
    rs0 += __shfl_xor_sync(0xFFFFFFFF, rs0, 1);
    rs0 += __shfl_xor_sync(0xFFFFFFFF, rs0, 2);
    rs1 += __shfl_xor_sync(0xFFFFFFFF, rs1, 1);
    rs1 += __shfl_xor_sync(0xFFFFFFFF, rs1, 2);
    const float inv0 = 1.0f / (rs0 + 1e-6f);
    const float inv1 = 1.0f / (rs1 + 1e-6f);

    {
        const int row0 = mr + g;
        float* ob = O + head + ((size_t)blockIdx.x * BM + row0) * DDIM;
        #pragma unroll
        for (int db = 0; db < 8; ++db) {
            int col = db * 8 + (lane & 3) * 2;
            float2 t0 = make_float2(OC[db][0] * inv0, OC[db][1] * inv0);
            float2 t1 = make_float2(OC[db][2] * inv1, OC[db][3] * inv1);
            *(float2*)(ob + col) = t0;
            *(float2*)(ob + 8 * DDIM + col) = t1;
        }
    }
}

extern "C" void kernel_launch(void* const* d_in, const int* in_sizes, int n_in,
                              void* d_out, int out_size) {
    const float* q = (const float*)d_in[0];
    const float* k = (const float*)d_in[1];
    const float* v = (const float*)d_in[2];
    float* o = (float*)d_out;

    const int BH = in_sizes[0] / (NQ * DDIM);   // 64 heads

    cudaFuncSetAttribute(power_attn_i8,
                         cudaFuncAttributeMaxDynamicSharedMemorySize, SMEM_BYTES);

    dim3 grid(NQ / BM, BH);
    power_attn_i8<<<grid, NTHREADS, SMEM_BYTES>>>(q, k, v, o);
}

// round 13
// speedup vs baseline: 3.9643x; 3.9643x over previous
#include <cuda_runtime.h>
#include <cuda_fp16.h>
#include <cstdint>

// PowerSoftmax attention via warp-level mma.sync (HMMA) — base sm_103 PTX.
//   S = (Q K^T)/8 ; P = S^2 ; O = (P / (rowsum(P)+1e-6)) V
// 64 heads of [2048, 64] fp32.
//
// Single-fp16 everywhere (error budget: dS ~3.4e-4 abs on s~N(0,1), PV fp16
// ~2.9e-4 -> total ~5e-4, 2x margin under the 1e-3 gate):
//   QK^T: 1 product (fp16 q x fp16 k, fp32 accum)
//   P V : 1 product (fp16 p x fp16 v, fp32 accum)
// Q A-fragments live in registers for the whole kv sweep.
// Denominator summed from the ROUNDED fp16 P (cancels rounding bias).

#define NQ       2048
#define DDIM     64
#define BM       128
#define BKV      128
#define NITER    (NQ / BKV)
#define NTHREADS 256

// smem byte offsets
#define B_K   0              // K fp16 [128 rows x 64 cols = 128B/row]  16 KB
#define B_V   16384          // Vt[d][kv] fp16 [64 rows x 256B]         16 KB
#define SMEM_BYTES 32768
// Prologue borrows B_K for the Q fp16 image before the loop overwrites it.

// K/Q tiles: [rows][64 x 2B = 128B]
__device__ __forceinline__ uint32_t sw_q(int row, int cb) {
    return (uint32_t)(row * 128 + (cb ^ ((row & 7) << 4)));
}
// Vt tile: [64 rows][128 kv x 2B = 256B]
__device__ __forceinline__ uint32_t sw_v(int row, int cb) {
    return (uint32_t)(row * 256 + (cb ^ ((row & 7) << 4)));
}

__device__ __forceinline__ void ldsm_x4(uint32_t* r, uint32_t addr) {
    asm volatile("ldmatrix.sync.aligned.m8n8.x4.shared.b16 {%0,%1,%2,%3}, [%4];"
                 : "=r"(r[0]), "=r"(r[1]), "=r"(r[2]), "=r"(r[3]) : "r"(addr));
}
__device__ __forceinline__ void mma_f16(float* c, const uint32_t* a, const uint32_t* b) {
    asm volatile("mma.sync.aligned.m16n8k16.row.col.f32.f16.f16.f32 "
                 "{%0,%1,%2,%3}, {%4,%5,%6,%7}, {%8,%9}, {%0,%1,%2,%3};"
                 : "+f"(c[0]), "+f"(c[1]), "+f"(c[2]), "+f"(c[3])
                 : "r"(a[0]), "r"(a[1]), "r"(a[2]), "r"(a[3]), "r"(b[0]), "r"(b[1]));
}

__global__ __launch_bounds__(NTHREADS, 2)
void power_attn_hmma(const float* __restrict__ Q, const float* __restrict__ K,
                     const float* __restrict__ V, float* __restrict__ O) {
    extern __shared__ char sm[];
    const uint32_t smb = (uint32_t)__cvta_generic_to_shared(sm);

    const int tid  = threadIdx.x;
    const int lane = tid & 31;
    const int wid  = tid >> 5;
    const int mr   = wid * 16;                 // warp's 16-row Q strip

    const size_t head = (size_t)blockIdx.y * NQ * DDIM;
    const float* qb = Q + head + (size_t)blockIdx.x * BM * DDIM;
    const float* kb = K + head;
    const float* vb = V + head;

    // ---- Stage Q tile -> fp16 image in B_K (temporary) ----
    {
        const float4* qg = (const float4*)qb;
        #pragma unroll
        for (int p = 0; p < 8; ++p) {
            int idx = tid + p * NTHREADS;            // 0..2047 float4s
            int row = idx >> 4;
            int c8  = (idx & 15) * 8;                // byte col in fp16 row
            float4 x = qg[idx];
            __half2 h01 = __floats2half2_rn(x.x, x.y);
            __half2 h23 = __floats2half2_rn(x.z, x.w);
            uint2 hh;
            hh.x = *(uint32_t*)&h01;
            hh.y = *(uint32_t*)&h23;
            *(uint2*)(sm + B_K + sw_q(row, c8)) = hh;
        }
    }
    __syncthreads();

    // ---- Hoist Q A-fragments for the whole kernel ----
    uint32_t Qf[4][4];
    {
        const int a_row = mr + (lane & 15);
        const int a_cbo = (lane >> 4) << 4;          // +0 / +16B
        #pragma unroll
        for (int ks = 0; ks < 4; ++ks)
            ldsm_x4(Qf[ks], smb + B_K + sw_q(a_row, ks * 32 + a_cbo));
    }

    float OC[8][4];                                  // O accum: 8 d-blocks
    #pragma unroll
    for (int d = 0; d < 8; ++d)
        #pragma unroll
        for (int r = 0; r < 4; ++r) OC[d][r] = 0.f;
    float rs0 = 0.f, rs1 = 0.f;                      // rowsum (rows l/4, l/4+8)

    // x4 B-fragment lane addressing (2 n-blocks per load)
    const int bx_row = (lane & 7) + ((lane >> 4) << 3);
    const int bx_cbo = ((lane >> 3) & 1) << 4;

    const int vpart = tid >> 6;                      // V convert: kv quarter
    const int vd    = tid & 63;

    for (int nt = 0; nt < NITER; ++nt) {
        __syncthreads();                 // prev tile consumed (and Q hoisted)

        // ---- K tile -> fp16 image ----
        const float4* kg = (const float4*)(kb + (size_t)nt * BKV * DDIM);
        #pragma unroll
        for (int p = 0; p < 8; ++p) {
            int idx = tid + p * NTHREADS;
            int row = idx >> 4;
            int c8  = (idx & 15) * 8;
            float4 x = kg[idx];
            __half2 h01 = __floats2half2_rn(x.x, x.y);
            __half2 h23 = __floats2half2_rn(x.z, x.w);
            uint2 hh;
            hh.x = *(uint32_t*)&h01;
            hh.y = *(uint32_t*)&h23;
            *(uint2*)(sm + B_K + sw_q(row, c8)) = hh;
        }

        // ---- V tile -> Vt[d][kv] fp16 (transposed), uint2 stores ----
        {
            const float* vg = vb + (size_t)nt * BKV * DDIM;
            #pragma unroll
            for (int i = 0; i < 8; ++i) {
                int kv = vpart * 32 + i * 4;
                float x0 = vg[(size_t)(kv + 0) * DDIM + vd];
                float x1 = vg[(size_t)(kv + 1) * DDIM + vd];
                float x2 = vg[(size_t)(kv + 2) * DDIM + vd];
                float x3 = vg[(size_t)(kv + 3) * DDIM + vd];
                __half2 ha = __floats2half2_rn(x0, x1);
                __half2 hb = __floats2half2_rn(x2, x3);
                uint2 u;
                u.x = *(uint32_t*)&ha;
                u.y = *(uint32_t*)&hb;
                *(uint2*)(sm + B_V + sw_v(vd, kv * 2)) = u;
            }
        }
        __syncthreads();

        #pragma unroll
        for (int h = 0; h < 2; ++h) {                // kv halves of 64
            // ---- QK^T: S[16 x 64] in C fragments ----
            float SC[8][4];
            #pragma unroll
            for (int nb = 0; nb < 8; ++nb)
                #pragma unroll
                for (int r = 0; r < 4; ++r) SC[nb][r] = 0.f;

            #pragma unroll
            for (int ks = 0; ks < 4; ++ks) {
                #pragma unroll
                for (int p = 0; p < 4; ++p) {        // n-block pairs
                    int n0 = h * 64 + p * 16;
                    uint32_t Bh[4];
                    ldsm_x4(Bh, smb + B_K + sw_q(n0 + bx_row, ks * 32 + bx_cbo));
                    mma_f16(SC[2 * p],     Qf[ks], Bh + 0);
                    mma_f16(SC[2 * p + 1], Qf[ks], Bh + 2);
                }
            }

            // ---- p = (s/8)^2, pack fp16 A-fragments, rowsum from rounded p ----
            uint32_t P[4][4];
            #pragma unroll
            for (int nb = 0; nb < 8; ++nb) {
                float s0 = SC[nb][0] * 0.125f, s1 = SC[nb][1] * 0.125f;
                float s2 = SC[nb][2] * 0.125f, s3 = SC[nb][3] * 0.125f;
                __half2 h01 = __floats2half2_rn(s0 * s0, s1 * s1);
                __half2 h23 = __floats2half2_rn(s2 * s2, s3 * s3);
                float2 f01 = __half22float2(h01);
                float2 f23 = __half22float2(h23);
                rs0 += f01.x + f01.y;
                rs1 += f23.x + f23.y;
                int kk = nb >> 1, hi = (nb & 1) * 2;
                P[kk][hi + 0] = *(uint32_t*)&h01;
                P[kk][hi + 1] = *(uint32_t*)&h23;
            }

            // ---- O += P V (fp16) ----
            #pragma unroll
            for (int kk = 0; kk < 4; ++kk) {
                int kvb = (h * 64 + kk * 16) * 2 + bx_cbo;   // byte col in Vt row
                #pragma unroll
                for (int dp = 0; dp < 4; ++dp) {             // d-block pairs
                    uint32_t Bv[4];
                    ldsm_x4(Bv, smb + B_V + sw_v(dp * 16 + bx_row, kvb));
                    mma_f16(OC[2 * dp],     P[kk], Bv + 0);
                    mma_f16(OC[2 * dp + 1], P[kk], Bv + 2);
                }
            }
        }
    }

    // ---- Rowsum reduce across the 4 lanes of each row group ----
    rs0 += __shfl_xor_sync(0xFFFFFFFF, rs0, 1);
    rs0 += __shfl_xor_sync(0xFFFFFFFF, rs0, 2);
    rs1 += __shfl_xor_sync(0xFFFFFFFF, rs1, 1);
    rs1 += __shfl_xor_sync(0xFFFFFFFF, rs1, 2);
    const float inv0 = 1.0f / (rs0 + 1e-6f);
    const float inv1 = 1.0f / (rs1 + 1e-6f);

    // ---- Store O ----
    {
        const int row0 = mr + (lane >> 2);
        float* ob = O + head + ((size_t)blockIdx.x * BM + row0) * DDIM;
        #pragma unroll
        for (int db = 0; db < 8; ++db) {
            int col = db * 8 + (lane & 3) * 2;
            float2 t0 = make_float2(OC[db][0] * inv0, OC[db][1] * inv0);
            float2 t1 = make_float2(OC[db][2] * inv1, OC[db][3] * inv1);
            *(float2*)(ob + col) = t0;
            *(float2*)(ob + 8 * DDIM + col) = t1;
        }
    }
}

extern "C" void kernel_launch(void* const* d_in, const int* in_sizes, int n_in,
                              void* d_out, int out_size) {
    const float* q = (const float*)d_in[0];
    const float* k = (const float*)d_in[1];
    const float* v = (const float*)d_in[2];
    float* o = (float*)d_out;

    const int BH = in_sizes[0] / (NQ * DDIM);   // 64 heads

    cudaFuncSetAttribute(power_attn_hmma,
                         cudaFuncAttributeMaxDynamicSharedMemorySize, SMEM_BYTES);

    dim3 grid(NQ / BM, BH);
    power_attn_hmma<<<grid, NTHREADS, SMEM_BYTES>>>(q, k, v, o);
}